// round 11
// baseline (speedup 1.0000x reference)
#include <cuda_runtime.h>
#include <math.h>
#include <stdint.h>

#define BB 2
#define SS 2048
#define DD 1024
#define HH 16
#define HDD 64
#define MR (BB*SS)   // 4096 rows

// Scratch (allocation-free rule: __device__ globals)
__device__ __align__(16) float    g_kv[MR * 2 * DD];   // kv proj out (tf32-rounded)
__device__ __align__(16) float    g_q [MR * DD];       // q  proj out (tf32-rounded)
__device__ __align__(16) float    g_av[MR * DD];       // attn out (B,H,S,HD), rounded
__device__ __align__(16) unsigned g_xc  [MR * DD];     // x     tf32 bits
__device__ __align__(16) unsigned g_yc  [MR * DD];     // y     tf32 bits
__device__ __align__(16) unsigned g_wkvc[DD * 2 * DD]; // W_kv  tf32 bits
__device__ __align__(16) unsigned g_wqc [DD * DD];     // W_q   tf32 bits
__device__ __align__(16) unsigned g_woc [DD * DD];     // W_o   tf32 bits

#define FULLMASK 0xffffffffu

__device__ __forceinline__ unsigned f2tf32(float f) {
    unsigned u;
    asm("cvt.rna.tf32.f32 %0, %1;" : "=r"(u) : "f"(f));
    return u;
}

__device__ __forceinline__ float ex2f(float x) {
    float y;
    asm("ex2.approx.f32 %0, %1;" : "=f"(y) : "f"(x));
    return y;
}

__device__ __forceinline__ void mma_tf32(float* d, const unsigned* a,
                                         unsigned b0, unsigned b1) {
    asm volatile(
        "mma.sync.aligned.m16n8k8.row.col.f32.tf32.tf32.f32 "
        "{%0,%1,%2,%3}, {%4,%5,%6,%7}, {%8,%9}, {%0,%1,%2,%3};\n"
        : "+f"(d[0]), "+f"(d[1]), "+f"(d[2]), "+f"(d[3])
        : "r"(a[0]), "r"(a[1]), "r"(a[2]), "r"(a[3]), "r"(b0), "r"(b1));
}

__device__ __forceinline__ void cp16(void* dst_smem, const void* src) {
    unsigned d = (unsigned)__cvta_generic_to_shared(dst_smem);
    asm volatile("cp.async.cg.shared.global [%0], [%1], 16;\n" :: "r"(d), "l"(src));
}
__device__ __forceinline__ void cp_commit() {
    asm volatile("cp.async.commit_group;\n");
}
template <int N> __device__ __forceinline__ void cp_wait() {
    asm volatile("cp.async.wait_group %0;\n" :: "n"(N));
}

// ---------------------------------------------------------------------------
// Single fused pre-round pass for all 5 tensors
// ---------------------------------------------------------------------------
#define N4_X   (MR * DD / 4)
#define N4_WKV (DD * 2 * DD / 4)
#define N4_W   (DD * DD / 4)
#define N4_TOT (2 * N4_X + N4_WKV + 2 * N4_W)

__global__ __launch_bounds__(256) void cvt_all_kernel(
    const float* __restrict__ x,   unsigned* __restrict__ xc,
    const float* __restrict__ y,   unsigned* __restrict__ yc,
    const float* __restrict__ wkv, unsigned* __restrict__ wkvc,
    const float* __restrict__ wq,  unsigned* __restrict__ wqc,
    const float* __restrict__ wo,  unsigned* __restrict__ woc)
{
    int i = blockIdx.x * 256 + threadIdx.x;
    const int E1 = N4_X, E2 = 2 * N4_X, E3 = E2 + N4_WKV, E4 = E3 + N4_W,
              E5 = E4 + N4_W;
    const float* s; unsigned* d; int j;
    if      (i < E1) { s = x;   d = xc;   j = i; }
    else if (i < E2) { s = y;   d = yc;   j = i - E1; }
    else if (i < E3) { s = wkv; d = wkvc; j = i - E2; }
    else if (i < E4) { s = wq;  d = wqc;  j = i - E3; }
    else if (i < E5) { s = wo;  d = woc;  j = i - E4; }
    else return;
    float4 v = *(const float4*)(s + 4 * (size_t)j);
    uint4 u = make_uint4(f2tf32(v.x), f2tf32(v.y), f2tf32(v.z), f2tf32(v.w));
    *(uint4*)(d + 4 * (size_t)j) = u;
}

// ---------------------------------------------------------------------------
// Tensor-core tf32 GEMM body, 3-stage cp.async pipeline, one barrier/K-tile.
// ---------------------------------------------------------------------------
#define TBM 128
#define TBN 128
#define TBK 32
#define ASTR 36
#define BSTR 136
#define ABUF (TBM * ASTR)   // 4608 words
#define BBUF (TBK * BSTR)   // 4352 words
#define NSTAGE 3
#define GEMM_SMEM (NSTAGE * (ABUF + BBUF) * 4)  // 107520 bytes

template <int ROUND>
__device__ __forceinline__ void gemm_body(
    const unsigned* __restrict__ A, const unsigned* __restrict__ Bm,
    const float* __restrict__ bias, float* __restrict__ C,
    int M, int N, int K, int bx, int by, unsigned* smg)
{
    unsigned* As = smg;                      // [NSTAGE][ABUF]
    unsigned* Bs = smg + NSTAGE * ABUF;      // [NSTAGE][BBUF]

    const int tid  = threadIdx.x;
    const int w    = tid >> 5;
    const int lane = tid & 31;
    const int g    = lane >> 2;
    const int t    = lane & 3;
    const int wm   = (w & 3) * 32;
    const int wn   = (w >> 2) * 64;
    const int brow = by * TBM;
    const int bcol = bx * TBN;

    float acc[2][8][4];
    #pragma unroll
    for (int mt = 0; mt < 2; mt++)
        #pragma unroll
        for (int nt = 0; nt < 8; nt++)
            #pragma unroll
            for (int j = 0; j < 4; j++) acc[mt][nt][j] = 0.f;

    auto load_tile = [&](int k0, int buf) {
        #pragma unroll
        for (int it = 0; it < 4; it++) {
            int i  = it * 256 + tid;
            int m  = i >> 3;
            int c4 = (i & 7) * 4;
            cp16(&As[buf * ABUF + m * ASTR + c4],
                 A + (size_t)(brow + m) * K + k0 + c4);
        }
        #pragma unroll
        for (int it = 0; it < 4; it++) {
            int i  = it * 256 + tid;
            int kk = i >> 5;
            int c4 = (i & 31) * 4;
            cp16(&Bs[buf * BBUF + kk * BSTR + c4],
                 Bm + (size_t)(k0 + kk) * N + bcol + c4);
        }
        cp_commit();
    };

    const int ntiles = K / TBK;
    load_tile(0, 0);
    load_tile(TBK, 1);

    for (int i = 0; i < ntiles; i++) {
        if (i + 1 < ntiles) cp_wait<1>();
        else                cp_wait<0>();
        __syncthreads();   // single barrier: also protects buf (i+2)%3 reuse
        if (i + 2 < ntiles) load_tile((i + 2) * TBK, (i + 2) % NSTAGE);

        const unsigned* Ab = &As[(i % NSTAGE) * ABUF];
        const unsigned* Bb = &Bs[(i % NSTAGE) * BBUF];
        #pragma unroll
        for (int ks = 0; ks < TBK / 8; ks++) {
            unsigned af[2][4];
            #pragma unroll
            for (int mt = 0; mt < 2; mt++) {
                const unsigned* ab = &Ab[(wm + mt * 16) * ASTR + ks * 8];
                af[mt][0] = ab[g * ASTR + t];
                af[mt][1] = ab[(g + 8) * ASTR + t];
                af[mt][2] = ab[g * ASTR + t + 4];
                af[mt][3] = ab[(g + 8) * ASTR + t + 4];
            }
            const unsigned* bb0 = &Bb[(ks * 8 + t) * BSTR + wn + g];
            const unsigned* bb1 = &Bb[(ks * 8 + t + 4) * BSTR + wn + g];
            #pragma unroll
            for (int nt = 0; nt < 8; nt++) {
                unsigned b0 = bb0[nt * 8];
                unsigned b1 = bb1[nt * 8];
                mma_tf32(acc[0][nt], af[0], b0, b1);
                mma_tf32(acc[1][nt], af[1], b0, b1);
            }
        }
    }

    // Epilogue: bias add (+ optional tf32 pre-round), coalesced float2 stores
    #pragma unroll
    for (int mt = 0; mt < 2; mt++) {
        const size_t r0 = (size_t)(brow + wm + mt * 16 + g);
        float* c0 = C + r0 * N;
        float* c1 = c0 + (size_t)8 * N;
        #pragma unroll
        for (int nt = 0; nt < 8; nt++) {
            int nc = bcol + wn + nt * 8 + 2 * t;
            float bx2 = bias[nc], by2 = bias[nc + 1];
            float v00 = acc[mt][nt][0] + bx2, v01 = acc[mt][nt][1] + by2;
            float v10 = acc[mt][nt][2] + bx2, v11 = acc[mt][nt][3] + by2;
            if (ROUND) {
                v00 = __uint_as_float(f2tf32(v00));
                v01 = __uint_as_float(f2tf32(v01));
                v10 = __uint_as_float(f2tf32(v10));
                v11 = __uint_as_float(f2tf32(v11));
            }
            *(float2*)&c0[nc] = make_float2(v00, v01);
            *(float2*)&c1[nc] = make_float2(v10, v11);
        }
    }
}

// Fused kv-proj + q-proj: blocks [0,512) do kv (N=2048), [512,768) do q.
__global__ __launch_bounds__(256, 2) void proj_fused_kernel(
    const unsigned* __restrict__ xc, const unsigned* __restrict__ wkv,
    const float* __restrict__ bkv, float* __restrict__ kvp,
    const unsigned* __restrict__ yc, const unsigned* __restrict__ wq,
    const float* __restrict__ bq, float* __restrict__ qp)
{
    extern __shared__ unsigned smg[];
    int bid = blockIdx.x;
    if (bid < 512) {
        gemm_body<1>(xc, wkv, bkv, kvp, MR, 2 * DD, DD, bid & 15, bid >> 4, smg);
    } else {
        int r = bid - 512;
        gemm_body<1>(yc, wq, bq, qp, MR, DD, DD, r & 7, r >> 3, smg);
    }
}

// Plain single GEMM (o-projection, no rounding)
__global__ __launch_bounds__(256, 2) void gemm_single_kernel(
    const unsigned* __restrict__ A, const unsigned* __restrict__ Bm,
    const float* __restrict__ bias, float* __restrict__ C,
    int M, int N, int K)
{
    extern __shared__ unsigned smg[];
    gemm_body<0>(A, Bm, bias, C, M, N, K, blockIdx.x, blockIdx.y, smg);
}

// ---------------------------------------------------------------------------
// Tensor-core flash attention, 512 threads (16 warps, BQ=256), 3-stage
// cp.async, log2-domain softmax. 16 warps share each KV tile -> 4 warps/SMSP
// and half the smem traffic per Q-row vs the 8-warp version.
// ---------------------------------------------------------------------------
#define KSTRIDE 68
#define VSTRIDE 72
#define KBUF (64 * KSTRIDE)
#define VBUF (64 * VSTRIDE)
#define ATTN_SMEM (NSTAGE * (KBUF + VBUF) * 4)
#define ATHREADS 512

__global__ __launch_bounds__(ATHREADS) void attn_tc_kernel(
    const float* __restrict__ q, const float* __restrict__ kv,
    float* __restrict__ out)
{
    extern __shared__ unsigned sma[];
    unsigned* k_u = sma;
    unsigned* v_u = sma + NSTAGE * KBUF;

    const int tid  = threadIdx.x;
    const int w    = tid >> 5;        // 0..15
    const int lane = tid & 31;
    const int g    = lane >> 2;
    const int t    = lane & 3;
    const int bh   = blockIdx.y;
    const int b    = bh / HH;
    const int h    = bh % HH;
    const int q0   = blockIdx.x * 256;

    const float* kvbase = kv + (size_t)b * SS * (2 * DD) + h * (2 * HDD);

    auto load_kv = [&](int kt, int buf) {
        #pragma unroll
        for (int it = 0; it < 2; it++) {
            int idx = it * ATHREADS + tid;
            int row = idx >> 4;
            int c4  = (idx & 15) * 4;
            const float* src = kvbase + (size_t)(kt + row) * (2 * DD) + c4;
            cp16(&k_u[buf * KBUF + row * KSTRIDE + c4], src);
            cp16(&v_u[buf * VBUF + row * VSTRIDE + c4], src + HDD);
        }
        cp_commit();
    };

    load_kv(0, 0);
    load_kv(64, 1);

    // Q fragments scaled by 0.125*log2e (log2-domain scores)
    const float QSCALE = 0.125f * 1.4426950408889634f;
    unsigned qa[8][4];
    {
        const float* q0p = q + (size_t)(b * SS + q0 + w * 16 + g) * DD + h * HDD;
        const float* q1p = q0p + (size_t)8 * DD;
        #pragma unroll
        for (int kj = 0; kj < 8; kj++) {
            qa[kj][0] = __float_as_uint(q0p[8 * kj + t]     * QSCALE);
            qa[kj][1] = __float_as_uint(q1p[8 * kj + t]     * QSCALE);
            qa[kj][2] = __float_as_uint(q0p[8 * kj + t + 4] * QSCALE);
            qa[kj][3] = __float_as_uint(q1p[8 * kj + t + 4] * QSCALE);
        }
    }

    float o[8][4];
    #pragma unroll
    for (int i = 0; i < 8; i++)
        #pragma unroll
        for (int j = 0; j < 4; j++) o[i][j] = 0.f;
    float m0 = -INFINITY, m1 = -INFINITY, l0 = 0.f, l1 = 0.f;

    const int ntiles = SS / 64;
    for (int i = 0; i < ntiles; i++) {
        if (i + 1 < ntiles) cp_wait<1>();
        else                cp_wait<0>();
        __syncthreads();
        if (i + 2 < ntiles) load_kv((i + 2) * 64, (i + 2) % NSTAGE);

        const unsigned* kb = &k_u[(i % NSTAGE) * KBUF];
        const unsigned* vb = &v_u[(i % NSTAGE) * VBUF];

        // S (log2 domain) = (Q * 0.125 * log2e) @ K^T
        float s[8][4];
        #pragma unroll
        for (int nt = 0; nt < 8; nt++) {
            s[nt][0] = s[nt][1] = s[nt][2] = s[nt][3] = 0.f;
            const unsigned* krow = &kb[(8 * nt + g) * KSTRIDE];
            #pragma unroll
            for (int kj = 0; kj < 8; kj++) {
                unsigned b0 = krow[8 * kj + t];
                unsigned b1 = krow[8 * kj + t + 4];
                mma_tf32(s[nt], qa[kj], b0, b1);
            }
        }

        // Online softmax in log2 domain (rows r0 = 16w+g, r1 = r0+8)
        float rmax0 = -INFINITY, rmax1 = -INFINITY;
        #pragma unroll
        for (int nt = 0; nt < 8; nt++) {
            rmax0 = fmaxf(rmax0, fmaxf(s[nt][0], s[nt][1]));
            rmax1 = fmaxf(rmax1, fmaxf(s[nt][2], s[nt][3]));
        }
        rmax0 = fmaxf(rmax0, __shfl_xor_sync(FULLMASK, rmax0, 1));
        rmax0 = fmaxf(rmax0, __shfl_xor_sync(FULLMASK, rmax0, 2));
        rmax1 = fmaxf(rmax1, __shfl_xor_sync(FULLMASK, rmax1, 1));
        rmax1 = fmaxf(rmax1, __shfl_xor_sync(FULLMASK, rmax1, 2));

        const float mn0 = fmaxf(m0, rmax0);
        const float mn1 = fmaxf(m1, rmax1);
        const float cr0 = ex2f(m0 - mn0);
        const float cr1 = ex2f(m1 - mn1);
        m0 = mn0; m1 = mn1;
        l0 *= cr0; l1 *= cr1;
        #pragma unroll
        for (int nt = 0; nt < 8; nt++) {
            o[nt][0] *= cr0; o[nt][1] *= cr0;
            o[nt][2] *= cr1; o[nt][3] *= cr1;
        }

        // ex2, row-sum, P -> A-fragment layout via shuffles
        const int srcA = (lane & 28) | (t >> 1);
        const int srcB = srcA | 2;
        const bool odd = (t & 1);
        unsigned pa[8][4];
        float ls0 = 0.f, ls1 = 0.f;
        #pragma unroll
        for (int nt = 0; nt < 8; nt++) {
            float p0 = ex2f(s[nt][0] - mn0);
            float p1 = ex2f(s[nt][1] - mn0);
            float p2 = ex2f(s[nt][2] - mn1);
            float p3 = ex2f(s[nt][3] - mn1);
            ls0 += p0 + p1; ls1 += p2 + p3;
            unsigned e0 = f2tf32(p0), e1 = f2tf32(p1);
            unsigned e2 = f2tf32(p2), e3 = f2tf32(p3);
            unsigned u0 = __shfl_sync(FULLMASK, e0, srcA);
            unsigned u1 = __shfl_sync(FULLMASK, e1, srcA);
            unsigned u2 = __shfl_sync(FULLMASK, e2, srcA);
            unsigned u3 = __shfl_sync(FULLMASK, e3, srcA);
            unsigned w0 = __shfl_sync(FULLMASK, e0, srcB);
            unsigned w1 = __shfl_sync(FULLMASK, e1, srcB);
            unsigned w2 = __shfl_sync(FULLMASK, e2, srcB);
            unsigned w3 = __shfl_sync(FULLMASK, e3, srcB);
            pa[nt][0] = odd ? u1 : u0;
            pa[nt][1] = odd ? u3 : u2;
            pa[nt][2] = odd ? w1 : w0;
            pa[nt][3] = odd ? w3 : w2;
        }
        ls0 += __shfl_xor_sync(FULLMASK, ls0, 1);
        ls0 += __shfl_xor_sync(FULLMASK, ls0, 2);
        ls1 += __shfl_xor_sync(FULLMASK, ls1, 1);
        ls1 += __shfl_xor_sync(FULLMASK, ls1, 2);
        l0 += ls0; l1 += ls1;

        // O += P @ V
        #pragma unroll
        for (int nd = 0; nd < 8; nd++) {
            #pragma unroll
            for (int kj = 0; kj < 8; kj++) {
                unsigned b0 = vb[(8 * kj + t)     * VSTRIDE + 8 * nd + g];
                unsigned b1 = vb[(8 * kj + t + 4) * VSTRIDE + 8 * nd + g];
                mma_tf32(o[nd], pa[kj], b0, b1);
            }
        }
    }

    // normalize + pre-round + store in (B,H,S,HD) layout
    const float inv0 = 1.f / l0;
    const float inv1 = 1.f / l1;
    const size_t r0 = (size_t)(b * HH + h) * SS + q0 + w * 16 + g;
    float* o0 = out + r0 * HDD;
    float* o1 = o0 + (size_t)8 * HDD;
    #pragma unroll
    for (int nt = 0; nt < 8; nt++) {
        int col = 8 * nt + 2 * t;
        float2 t0 = make_float2(__uint_as_float(f2tf32(o[nt][0] * inv0)),
                                __uint_as_float(f2tf32(o[nt][1] * inv0)));
        float2 t1 = make_float2(__uint_as_float(f2tf32(o[nt][2] * inv1)),
                                __uint_as_float(f2tf32(o[nt][3] * inv1)));
        *(float2*)&o0[col] = t0;
        *(float2*)&o1[col] = t1;
    }
}

// ---------------------------------------------------------------------------
extern "C" void kernel_launch(void* const* d_in, const int* in_sizes, int n_in,
                              void* d_out, int out_size)
{
    const float* x    = (const float*)d_in[0];
    const float* y    = (const float*)d_in[1];
    const float* W_kv = (const float*)d_in[2];
    const float* b_kv = (const float*)d_in[3];
    const float* W_q  = (const float*)d_in[4];
    const float* b_q  = (const float*)d_in[5];
    const float* W_o  = (const float*)d_in[6];
    const float* b_o  = (const float*)d_in[7];
    float* out = (float*)d_out;

    float *kvp, *qp, *avp;
    unsigned *xc, *yc, *wkvc, *wqc, *woc;
    cudaGetSymbolAddress((void**)&kvp,  g_kv);
    cudaGetSymbolAddress((void**)&qp,   g_q);
    cudaGetSymbolAddress((void**)&avp,  g_av);
    cudaGetSymbolAddress((void**)&xc,   g_xc);
    cudaGetSymbolAddress((void**)&yc,   g_yc);
    cudaGetSymbolAddress((void**)&wkvc, g_wkvc);
    cudaGetSymbolAddress((void**)&wqc,  g_wqc);
    cudaGetSymbolAddress((void**)&woc,  g_woc);

    cudaFuncSetAttribute(proj_fused_kernel,
        cudaFuncAttributeMaxDynamicSharedMemorySize, GEMM_SMEM);
    cudaFuncSetAttribute(gemm_single_kernel,
        cudaFuncAttributeMaxDynamicSharedMemorySize, GEMM_SMEM);
    cudaFuncSetAttribute(attn_tc_kernel,
        cudaFuncAttributeMaxDynamicSharedMemorySize, ATTN_SMEM);

    // Single fused pre-round pass for all 5 tensors
    cvt_all_kernel<<<(N4_TOT + 255) / 256, 256>>>(
        x, xc, y, yc, W_kv, wkvc, W_q, wqc, W_o, woc);

    // Fused kv-proj + q-proj (768 blocks, 2 CTAs/SM), outputs pre-rounded
    proj_fused_kernel<<<768, 256, GEMM_SMEM>>>(
        xc, wkvc, b_kv, kvp, yc, wqc, b_q, qp);

    // fused tensor-core attention (512 threads, BQ=256) -> g_av
    attn_tc_kernel<<<dim3(SS / 256, BB * HH), ATHREADS, ATTN_SMEM>>>(
        qp, kvp, avp);

    // out = values @ W_o + b_o [4096 x 1024]
    gemm_single_kernel<<<dim3(DD / TBN, MR / TBM), 256, GEMM_SMEM>>>(
        (const unsigned*)avp, woc, b_o, out, MR, DD, DD);
}

// round 12
// speedup vs baseline: 1.5476x; 1.5476x over previous
#include <cuda_runtime.h>
#include <math.h>
#include <stdint.h>

#define BB 2
#define SS 2048
#define DD 1024
#define HH 16
#define HDD 64
#define MR (BB*SS)   // 4096 rows

// Scratch (allocation-free rule: __device__ globals)
__device__ __align__(16) float    g_kv[MR * 2 * DD];   // kv proj out (tf32-rounded)
__device__ __align__(16) float    g_q [MR * DD];       // q  proj out (tf32-rounded)
__device__ __align__(16) float    g_av[MR * DD];       // attn out (B,H,S,HD), rounded
__device__ __align__(16) unsigned g_xc  [MR * DD];     // x     tf32 bits
__device__ __align__(16) unsigned g_yc  [MR * DD];     // y     tf32 bits
__device__ __align__(16) unsigned g_wkvc[DD * 2 * DD]; // W_kv  tf32 bits
__device__ __align__(16) unsigned g_wqc [DD * DD];     // W_q   tf32 bits
__device__ __align__(16) unsigned g_woc [DD * DD];     // W_o   tf32 bits

#define FULLMASK 0xffffffffu

__device__ __forceinline__ unsigned f2tf32(float f) {
    unsigned u;
    asm("cvt.rna.tf32.f32 %0, %1;" : "=r"(u) : "f"(f));
    return u;
}

__device__ __forceinline__ float ex2f(float x) {
    float y;
    asm("ex2.approx.f32 %0, %1;" : "=f"(y) : "f"(x));
    return y;
}

__device__ __forceinline__ void mma_tf32(float* d, const unsigned* a,
                                         unsigned b0, unsigned b1) {
    asm volatile(
        "mma.sync.aligned.m16n8k8.row.col.f32.tf32.tf32.f32 "
        "{%0,%1,%2,%3}, {%4,%5,%6,%7}, {%8,%9}, {%0,%1,%2,%3};\n"
        : "+f"(d[0]), "+f"(d[1]), "+f"(d[2]), "+f"(d[3])
        : "r"(a[0]), "r"(a[1]), "r"(a[2]), "r"(a[3]), "r"(b0), "r"(b1));
}

__device__ __forceinline__ void cp16(void* dst_smem, const void* src) {
    unsigned d = (unsigned)__cvta_generic_to_shared(dst_smem);
    asm volatile("cp.async.cg.shared.global [%0], [%1], 16;\n" :: "r"(d), "l"(src));
}
__device__ __forceinline__ void cp_commit() {
    asm volatile("cp.async.commit_group;\n");
}
template <int N> __device__ __forceinline__ void cp_wait() {
    asm volatile("cp.async.wait_group %0;\n" :: "n"(N));
}

// ---------------------------------------------------------------------------
// Single fused pre-round pass for all 5 tensors
// ---------------------------------------------------------------------------
#define N4_X   (MR * DD / 4)
#define N4_WKV (DD * 2 * DD / 4)
#define N4_W   (DD * DD / 4)
#define N4_TOT (2 * N4_X + N4_WKV + 2 * N4_W)

__global__ __launch_bounds__(256) void cvt_all_kernel(
    const float* __restrict__ x,   unsigned* __restrict__ xc,
    const float* __restrict__ y,   unsigned* __restrict__ yc,
    const float* __restrict__ wkv, unsigned* __restrict__ wkvc,
    const float* __restrict__ wq,  unsigned* __restrict__ wqc,
    const float* __restrict__ wo,  unsigned* __restrict__ woc)
{
    int i = blockIdx.x * 256 + threadIdx.x;
    const int E1 = N4_X, E2 = 2 * N4_X, E3 = E2 + N4_WKV, E4 = E3 + N4_W,
              E5 = E4 + N4_W;
    const float* s; unsigned* d; int j;
    if      (i < E1) { s = x;   d = xc;   j = i; }
    else if (i < E2) { s = y;   d = yc;   j = i - E1; }
    else if (i < E3) { s = wkv; d = wkvc; j = i - E2; }
    else if (i < E4) { s = wq;  d = wqc;  j = i - E3; }
    else if (i < E5) { s = wo;  d = woc;  j = i - E4; }
    else return;
    float4 v = *(const float4*)(s + 4 * (size_t)j);
    uint4 u = make_uint4(f2tf32(v.x), f2tf32(v.y), f2tf32(v.z), f2tf32(v.w));
    *(uint4*)(d + 4 * (size_t)j) = u;
}

// ---------------------------------------------------------------------------
// Tensor-core tf32 GEMM body, 3-stage cp.async pipeline, one barrier/K-tile.
// (R10 configuration: NO min-blocks clamp — that regressed in R11.)
// ---------------------------------------------------------------------------
#define TBM 128
#define TBN 128
#define TBK 32
#define ASTR 36
#define BSTR 136
#define ABUF (TBM * ASTR)   // 4608 words
#define BBUF (TBK * BSTR)   // 4352 words
#define NSTAGE 3
#define GEMM_SMEM (NSTAGE * (ABUF + BBUF) * 4)  // 107520 bytes

template <int ROUND>
__device__ __forceinline__ void gemm_body(
    const unsigned* __restrict__ A, const unsigned* __restrict__ Bm,
    const float* __restrict__ bias, float* __restrict__ C,
    int M, int N, int K, int bx, int by, unsigned* smg)
{
    unsigned* As = smg;                      // [NSTAGE][ABUF]
    unsigned* Bs = smg + NSTAGE * ABUF;      // [NSTAGE][BBUF]

    const int tid  = threadIdx.x;
    const int w    = tid >> 5;
    const int lane = tid & 31;
    const int g    = lane >> 2;
    const int t    = lane & 3;
    const int wm   = (w & 3) * 32;
    const int wn   = (w >> 2) * 64;
    const int brow = by * TBM;
    const int bcol = bx * TBN;

    float acc[2][8][4];
    #pragma unroll
    for (int mt = 0; mt < 2; mt++)
        #pragma unroll
        for (int nt = 0; nt < 8; nt++)
            #pragma unroll
            for (int j = 0; j < 4; j++) acc[mt][nt][j] = 0.f;

    auto load_tile = [&](int k0, int buf) {
        #pragma unroll
        for (int it = 0; it < 4; it++) {
            int i  = it * 256 + tid;
            int m  = i >> 3;
            int c4 = (i & 7) * 4;
            cp16(&As[buf * ABUF + m * ASTR + c4],
                 A + (size_t)(brow + m) * K + k0 + c4);
        }
        #pragma unroll
        for (int it = 0; it < 4; it++) {
            int i  = it * 256 + tid;
            int kk = i >> 5;
            int c4 = (i & 31) * 4;
            cp16(&Bs[buf * BBUF + kk * BSTR + c4],
                 Bm + (size_t)(k0 + kk) * N + bcol + c4);
        }
        cp_commit();
    };

    const int ntiles = K / TBK;
    load_tile(0, 0);
    load_tile(TBK, 1);

    for (int i = 0; i < ntiles; i++) {
        if (i + 1 < ntiles) cp_wait<1>();
        else                cp_wait<0>();
        __syncthreads();   // single barrier: also protects buf (i+2)%3 reuse
        if (i + 2 < ntiles) load_tile((i + 2) * TBK, (i + 2) % NSTAGE);

        const unsigned* Ab = &As[(i % NSTAGE) * ABUF];
        const unsigned* Bb = &Bs[(i % NSTAGE) * BBUF];
        #pragma unroll
        for (int ks = 0; ks < TBK / 8; ks++) {
            unsigned af[2][4];
            #pragma unroll
            for (int mt = 0; mt < 2; mt++) {
                const unsigned* ab = &Ab[(wm + mt * 16) * ASTR + ks * 8];
                af[mt][0] = ab[g * ASTR + t];
                af[mt][1] = ab[(g + 8) * ASTR + t];
                af[mt][2] = ab[g * ASTR + t + 4];
                af[mt][3] = ab[(g + 8) * ASTR + t + 4];
            }
            const unsigned* bb0 = &Bb[(ks * 8 + t) * BSTR + wn + g];
            const unsigned* bb1 = &Bb[(ks * 8 + t + 4) * BSTR + wn + g];
            #pragma unroll
            for (int nt = 0; nt < 8; nt++) {
                unsigned b0 = bb0[nt * 8];
                unsigned b1 = bb1[nt * 8];
                mma_tf32(acc[0][nt], af[0], b0, b1);
                mma_tf32(acc[1][nt], af[1], b0, b1);
            }
        }
    }

    // Epilogue: bias add (+ optional tf32 pre-round), coalesced float2 stores
    #pragma unroll
    for (int mt = 0; mt < 2; mt++) {
        const size_t r0 = (size_t)(brow + wm + mt * 16 + g);
        float* c0 = C + r0 * N;
        float* c1 = c0 + (size_t)8 * N;
        #pragma unroll
        for (int nt = 0; nt < 8; nt++) {
            int nc = bcol + wn + nt * 8 + 2 * t;
            float bx2 = bias[nc], by2 = bias[nc + 1];
            float v00 = acc[mt][nt][0] + bx2, v01 = acc[mt][nt][1] + by2;
            float v10 = acc[mt][nt][2] + bx2, v11 = acc[mt][nt][3] + by2;
            if (ROUND) {
                v00 = __uint_as_float(f2tf32(v00));
                v01 = __uint_as_float(f2tf32(v01));
                v10 = __uint_as_float(f2tf32(v10));
                v11 = __uint_as_float(f2tf32(v11));
            }
            *(float2*)&c0[nc] = make_float2(v00, v01);
            *(float2*)&c1[nc] = make_float2(v10, v11);
        }
    }
}

// Fused kv-proj + q-proj: blocks [0,512) do kv (N=2048), [512,768) do q.
__global__ __launch_bounds__(256) void proj_fused_kernel(
    const unsigned* __restrict__ xc, const unsigned* __restrict__ wkv,
    const float* __restrict__ bkv, float* __restrict__ kvp,
    const unsigned* __restrict__ yc, const unsigned* __restrict__ wq,
    const float* __restrict__ bq, float* __restrict__ qp)
{
    extern __shared__ unsigned smg[];
    int bid = blockIdx.x;
    if (bid < 512) {
        gemm_body<1>(xc, wkv, bkv, kvp, MR, 2 * DD, DD, bid & 15, bid >> 4, smg);
    } else {
        int r = bid - 512;
        gemm_body<1>(yc, wq, bq, qp, MR, DD, DD, r & 7, r >> 3, smg);
    }
}

// Plain single GEMM (o-projection, no rounding)
__global__ __launch_bounds__(256) void gemm_single_kernel(
    const unsigned* __restrict__ A, const unsigned* __restrict__ Bm,
    const float* __restrict__ bias, float* __restrict__ C,
    int M, int N, int K)
{
    extern __shared__ unsigned smg[];
    gemm_body<0>(A, Bm, bias, C, M, N, K, blockIdx.x, blockIdx.y, smg);
}

// ---------------------------------------------------------------------------
// Tensor-core flash attention: 256 threads / 8 warps, each warp owns
// 32 Q-rows (2 m-fragment groups). Every K/V B-fragment pair is loaded from
// smem ONCE and feeds TWO MMAs -> smem crossbar bytes per FLOP halve vs the
// 16-row version (which was crossbar-bound at ~2:1 LDS:MMA cycles).
// 3-stage cp.async pipeline, log2-domain softmax.
// ---------------------------------------------------------------------------
#define KSTRIDE 68
#define VSTRIDE 72
#define KBUF (64 * KSTRIDE)
#define VBUF (64 * VSTRIDE)
#define ATTN_SMEM (NSTAGE * (KBUF + VBUF) * 4)

__global__ __launch_bounds__(256, 1) void attn_tc_kernel(
    const float* __restrict__ q, const float* __restrict__ kv,
    float* __restrict__ out)
{
    extern __shared__ unsigned sma[];
    unsigned* k_u = sma;
    unsigned* v_u = sma + NSTAGE * KBUF;

    const int tid  = threadIdx.x;
    const int w    = tid >> 5;
    const int lane = tid & 31;
    const int g    = lane >> 2;
    const int t    = lane & 3;
    const int bh   = blockIdx.y;
    const int b    = bh / HH;
    const int h    = bh % HH;
    const int q0   = blockIdx.x * 256;   // BQ=256: 8 warps x 32 rows

    const float* kvbase = kv + (size_t)b * SS * (2 * DD) + h * (2 * HDD);

    auto load_kv = [&](int kt, int buf) {
        #pragma unroll
        for (int it = 0; it < 4; it++) {
            int idx = it * 256 + tid;
            int row = idx >> 4;
            int c4  = (idx & 15) * 4;
            const float* src = kvbase + (size_t)(kt + row) * (2 * DD) + c4;
            cp16(&k_u[buf * KBUF + row * KSTRIDE + c4], src);
            cp16(&v_u[buf * VBUF + row * VSTRIDE + c4], src + HDD);
        }
        cp_commit();
    };

    load_kv(0, 0);
    load_kv(64, 1);

    // Q fragments for both 16-row groups, scaled by 0.125*log2e
    const float QSCALE = 0.125f * 1.4426950408889634f;
    unsigned qa[2][8][4];
    #pragma unroll
    for (int mt = 0; mt < 2; mt++) {
        const float* q0p = q + (size_t)(b * SS + q0 + w * 32 + mt * 16 + g) * DD
                             + h * HDD;
        const float* q1p = q0p + (size_t)8 * DD;
        #pragma unroll
        for (int kj = 0; kj < 8; kj++) {
            qa[mt][kj][0] = __float_as_uint(q0p[8 * kj + t]     * QSCALE);
            qa[mt][kj][1] = __float_as_uint(q1p[8 * kj + t]     * QSCALE);
            qa[mt][kj][2] = __float_as_uint(q0p[8 * kj + t + 4] * QSCALE);
            qa[mt][kj][3] = __float_as_uint(q1p[8 * kj + t + 4] * QSCALE);
        }
    }

    float o[2][8][4];
    #pragma unroll
    for (int mt = 0; mt < 2; mt++)
        #pragma unroll
        for (int i = 0; i < 8; i++)
            #pragma unroll
            for (int j = 0; j < 4; j++) o[mt][i][j] = 0.f;
    float mH[2][2], lH[2][2];
    #pragma unroll
    for (int mt = 0; mt < 2; mt++) {
        mH[mt][0] = -INFINITY; mH[mt][1] = -INFINITY;
        lH[mt][0] = 0.f;       lH[mt][1] = 0.f;
    }

    const int ntiles = SS / 64;
    for (int i = 0; i < ntiles; i++) {
        if (i + 1 < ntiles) cp_wait<1>();
        else                cp_wait<0>();
        __syncthreads();
        if (i + 2 < ntiles) load_kv((i + 2) * 64, (i + 2) % NSTAGE);

        const unsigned* kb = &k_u[(i % NSTAGE) * KBUF];
        const unsigned* vb = &v_u[(i % NSTAGE) * VBUF];

        // S = Q @ K^T : each K b-frag feeds BOTH m-groups
        float s[2][8][4];
        #pragma unroll
        for (int nt = 0; nt < 8; nt++) {
            #pragma unroll
            for (int mt = 0; mt < 2; mt++)
                s[mt][nt][0] = s[mt][nt][1] = s[mt][nt][2] = s[mt][nt][3] = 0.f;
            const unsigned* krow = &kb[(8 * nt + g) * KSTRIDE];
            #pragma unroll
            for (int kj = 0; kj < 8; kj++) {
                unsigned b0 = krow[8 * kj + t];
                unsigned b1 = krow[8 * kj + t + 4];
                mma_tf32(s[0][nt], qa[0][kj], b0, b1);
                mma_tf32(s[1][nt], qa[1][kj], b0, b1);
            }
        }

        // Online softmax (log2 domain), per m-group
        unsigned pa[2][8][4];
        #pragma unroll
        for (int mt = 0; mt < 2; mt++) {
            float rmax0 = -INFINITY, rmax1 = -INFINITY;
            #pragma unroll
            for (int nt = 0; nt < 8; nt++) {
                rmax0 = fmaxf(rmax0, fmaxf(s[mt][nt][0], s[mt][nt][1]));
                rmax1 = fmaxf(rmax1, fmaxf(s[mt][nt][2], s[mt][nt][3]));
            }
            rmax0 = fmaxf(rmax0, __shfl_xor_sync(FULLMASK, rmax0, 1));
            rmax0 = fmaxf(rmax0, __shfl_xor_sync(FULLMASK, rmax0, 2));
            rmax1 = fmaxf(rmax1, __shfl_xor_sync(FULLMASK, rmax1, 1));
            rmax1 = fmaxf(rmax1, __shfl_xor_sync(FULLMASK, rmax1, 2));

            const float mn0 = fmaxf(mH[mt][0], rmax0);
            const float mn1 = fmaxf(mH[mt][1], rmax1);
            const float cr0 = ex2f(mH[mt][0] - mn0);
            const float cr1 = ex2f(mH[mt][1] - mn1);
            mH[mt][0] = mn0; mH[mt][1] = mn1;
            lH[mt][0] *= cr0; lH[mt][1] *= cr1;
            #pragma unroll
            for (int nt = 0; nt < 8; nt++) {
                o[mt][nt][0] *= cr0; o[mt][nt][1] *= cr0;
                o[mt][nt][2] *= cr1; o[mt][nt][3] *= cr1;
            }

            const int srcA = (lane & 28) | (t >> 1);
            const int srcB = srcA | 2;
            const bool odd = (t & 1);
            float ls0 = 0.f, ls1 = 0.f;
            #pragma unroll
            for (int nt = 0; nt < 8; nt++) {
                float p0 = ex2f(s[mt][nt][0] - mn0);
                float p1 = ex2f(s[mt][nt][1] - mn0);
                float p2 = ex2f(s[mt][nt][2] - mn1);
                float p3 = ex2f(s[mt][nt][3] - mn1);
                ls0 += p0 + p1; ls1 += p2 + p3;
                unsigned e0 = f2tf32(p0), e1 = f2tf32(p1);
                unsigned e2 = f2tf32(p2), e3 = f2tf32(p3);
                unsigned u0 = __shfl_sync(FULLMASK, e0, srcA);
                unsigned u1 = __shfl_sync(FULLMASK, e1, srcA);
                unsigned u2 = __shfl_sync(FULLMASK, e2, srcA);
                unsigned u3 = __shfl_sync(FULLMASK, e3, srcA);
                unsigned w0 = __shfl_sync(FULLMASK, e0, srcB);
                unsigned w1 = __shfl_sync(FULLMASK, e1, srcB);
                unsigned w2 = __shfl_sync(FULLMASK, e2, srcB);
                unsigned w3 = __shfl_sync(FULLMASK, e3, srcB);
                pa[mt][nt][0] = odd ? u1 : u0;
                pa[mt][nt][1] = odd ? u3 : u2;
                pa[mt][nt][2] = odd ? w1 : w0;
                pa[mt][nt][3] = odd ? w3 : w2;
            }
            ls0 += __shfl_xor_sync(FULLMASK, ls0, 1);
            ls0 += __shfl_xor_sync(FULLMASK, ls0, 2);
            ls1 += __shfl_xor_sync(FULLMASK, ls1, 1);
            ls1 += __shfl_xor_sync(FULLMASK, ls1, 2);
            lH[mt][0] += ls0; lH[mt][1] += ls1;
        }

        // O += P @ V : each V b-frag feeds BOTH m-groups
        #pragma unroll
        for (int nd = 0; nd < 8; nd++) {
            #pragma unroll
            for (int kj = 0; kj < 8; kj++) {
                unsigned b0 = vb[(8 * kj + t)     * VSTRIDE + 8 * nd + g];
                unsigned b1 = vb[(8 * kj + t + 4) * VSTRIDE + 8 * nd + g];
                mma_tf32(o[0][nd], pa[0][kj], b0, b1);
                mma_tf32(o[1][nd], pa[1][kj], b0, b1);
            }
        }
    }

    // normalize + pre-round + store in (B,H,S,HD) layout
    #pragma unroll
    for (int mt = 0; mt < 2; mt++) {
        const float inv0 = 1.f / lH[mt][0];
        const float inv1 = 1.f / lH[mt][1];
        const size_t r0 = (size_t)(b * HH + h) * SS + q0 + w * 32 + mt * 16 + g;
        float* o0 = out + r0 * HDD;
        float* o1 = o0 + (size_t)8 * HDD;
        #pragma unroll
        for (int nt = 0; nt < 8; nt++) {
            int col = 8 * nt + 2 * t;
            float2 t0 = make_float2(__uint_as_float(f2tf32(o[mt][nt][0] * inv0)),
                                    __uint_as_float(f2tf32(o[mt][nt][1] * inv0)));
            float2 t1 = make_float2(__uint_as_float(f2tf32(o[mt][nt][2] * inv1)),
                                    __uint_as_float(f2tf32(o[mt][nt][3] * inv1)));
            *(float2*)&o0[col] = t0;
            *(float2*)&o1[col] = t1;
        }
    }
}

// ---------------------------------------------------------------------------
extern "C" void kernel_launch(void* const* d_in, const int* in_sizes, int n_in,
                              void* d_out, int out_size)
{
    const float* x    = (const float*)d_in[0];
    const float* y    = (const float*)d_in[1];
    const float* W_kv = (const float*)d_in[2];
    const float* b_kv = (const float*)d_in[3];
    const float* W_q  = (const float*)d_in[4];
    const float* b_q  = (const float*)d_in[5];
    const float* W_o  = (const float*)d_in[6];
    const float* b_o  = (const float*)d_in[7];
    float* out = (float*)d_out;

    float *kvp, *qp, *avp;
    unsigned *xc, *yc, *wkvc, *wqc, *woc;
    cudaGetSymbolAddress((void**)&kvp,  g_kv);
    cudaGetSymbolAddress((void**)&qp,   g_q);
    cudaGetSymbolAddress((void**)&avp,  g_av);
    cudaGetSymbolAddress((void**)&xc,   g_xc);
    cudaGetSymbolAddress((void**)&yc,   g_yc);
    cudaGetSymbolAddress((void**)&wkvc, g_wkvc);
    cudaGetSymbolAddress((void**)&wqc,  g_wqc);
    cudaGetSymbolAddress((void**)&woc,  g_woc);

    cudaFuncSetAttribute(proj_fused_kernel,
        cudaFuncAttributeMaxDynamicSharedMemorySize, GEMM_SMEM);
    cudaFuncSetAttribute(gemm_single_kernel,
        cudaFuncAttributeMaxDynamicSharedMemorySize, GEMM_SMEM);
    cudaFuncSetAttribute(attn_tc_kernel,
        cudaFuncAttributeMaxDynamicSharedMemorySize, ATTN_SMEM);

    // Single fused pre-round pass for all 5 tensors
    cvt_all_kernel<<<(N4_TOT + 255) / 256, 256>>>(
        x, xc, y, yc, W_kv, wkvc, W_q, wqc, W_o, woc);

    // Fused kv-proj + q-proj (768 blocks), outputs pre-rounded
    proj_fused_kernel<<<768, 256, GEMM_SMEM>>>(
        xc, wkvc, b_kv, kvp, yc, wqc, b_q, qp);

    // fused tensor-core attention (256 threads, 32 rows/warp) -> g_av
    attn_tc_kernel<<<dim3(SS / 256, BB * HH), 256, ATTN_SMEM>>>(
        qp, kvp, avp);

    // out = values @ W_o + b_o [4096 x 1024]
    gemm_single_kernel<<<dim3(DD / TBN, MR / TBM), 256, GEMM_SMEM>>>(
        (const unsigned*)avp, woc, b_o, out, MR, DD, DD);
}

// round 13
// speedup vs baseline: 1.5996x; 1.0336x over previous
#include <cuda_runtime.h>
#include <math.h>
#include <stdint.h>

#define BB 2
#define SS 2048
#define DD 1024
#define HH 16
#define HDD 64
#define MR (BB*SS)   // 4096 rows

// Scratch (allocation-free rule: __device__ globals)
__device__ __align__(16) float    g_kv[MR * 2 * DD];   // kv proj out (tf32-rounded)
__device__ __align__(16) float    g_q [MR * DD];       // q  proj out (tf32-rounded)
__device__ __align__(16) float    g_av[MR * DD];       // attn out (B,H,S,HD), rounded
__device__ __align__(16) unsigned g_xc  [MR * DD];     // x     tf32 bits
__device__ __align__(16) unsigned g_yc  [MR * DD];     // y     tf32 bits
__device__ __align__(16) unsigned g_wkvc[DD * 2 * DD]; // W_kv  tf32 bits
__device__ __align__(16) unsigned g_wqc [DD * DD];     // W_q   tf32 bits
__device__ __align__(16) unsigned g_woc [DD * DD];     // W_o   tf32 bits

#define FULLMASK 0xffffffffu

__device__ __forceinline__ unsigned f2tf32(float f) {
    unsigned u;
    asm("cvt.rna.tf32.f32 %0, %1;" : "=r"(u) : "f"(f));
    return u;
}

__device__ __forceinline__ float ex2f(float x) {
    float y;
    asm("ex2.approx.f32 %0, %1;" : "=f"(y) : "f"(x));
    return y;
}

__device__ __forceinline__ void mma_tf32(float* d, const unsigned* a,
                                         unsigned b0, unsigned b1) {
    asm volatile(
        "mma.sync.aligned.m16n8k8.row.col.f32.tf32.tf32.f32 "
        "{%0,%1,%2,%3}, {%4,%5,%6,%7}, {%8,%9}, {%0,%1,%2,%3};\n"
        : "+f"(d[0]), "+f"(d[1]), "+f"(d[2]), "+f"(d[3])
        : "r"(a[0]), "r"(a[1]), "r"(a[2]), "r"(a[3]), "r"(b0), "r"(b1));
}

__device__ __forceinline__ void cp16(void* dst_smem, const void* src) {
    unsigned d = (unsigned)__cvta_generic_to_shared(dst_smem);
    asm volatile("cp.async.cg.shared.global [%0], [%1], 16;\n" :: "r"(d), "l"(src));
}
__device__ __forceinline__ void cp_commit() {
    asm volatile("cp.async.commit_group;\n");
}
template <int N> __device__ __forceinline__ void cp_wait() {
    asm volatile("cp.async.wait_group %0;\n" :: "n"(N));
}

// ---------------------------------------------------------------------------
// Single fused pre-round pass for all 5 tensors
// ---------------------------------------------------------------------------
#define N4_X   (MR * DD / 4)
#define N4_WKV (DD * 2 * DD / 4)
#define N4_W   (DD * DD / 4)
#define N4_TOT (2 * N4_X + N4_WKV + 2 * N4_W)

__global__ __launch_bounds__(256) void cvt_all_kernel(
    const float* __restrict__ x,   unsigned* __restrict__ xc,
    const float* __restrict__ y,   unsigned* __restrict__ yc,
    const float* __restrict__ wkv, unsigned* __restrict__ wkvc,
    const float* __restrict__ wq,  unsigned* __restrict__ wqc,
    const float* __restrict__ wo,  unsigned* __restrict__ woc)
{
    int i = blockIdx.x * 256 + threadIdx.x;
    const int E1 = N4_X, E2 = 2 * N4_X, E3 = E2 + N4_WKV, E4 = E3 + N4_W,
              E5 = E4 + N4_W;
    const float* s; unsigned* d; int j;
    if      (i < E1) { s = x;   d = xc;   j = i; }
    else if (i < E2) { s = y;   d = yc;   j = i - E1; }
    else if (i < E3) { s = wkv; d = wkvc; j = i - E2; }
    else if (i < E4) { s = wq;  d = wqc;  j = i - E3; }
    else if (i < E5) { s = wo;  d = woc;  j = i - E4; }
    else return;
    float4 v = *(const float4*)(s + 4 * (size_t)j);
    uint4 u = make_uint4(f2tf32(v.x), f2tf32(v.y), f2tf32(v.z), f2tf32(v.w));
    *(uint4*)(d + 4 * (size_t)j) = u;
}

// ---------------------------------------------------------------------------
// Tensor-core tf32 GEMM body, 2-stage cp.async, 2 CTAs/SM (16 warps/SM).
// 71.7KB smem/CTA x 2 = 143KB < 228KB carveout; regs ~96 -> fits.
// ---------------------------------------------------------------------------
#define TBM 128
#define TBN 128
#define TBK 32
#define ASTR 36
#define BSTR 136
#define ABUF (TBM * ASTR)   // 4608 words
#define BBUF (TBK * BSTR)   // 4352 words
#define NGSTAGE 2
#define GEMM_SMEM (NGSTAGE * (ABUF + BBUF) * 4)  // 71680 bytes

template <int ROUND>
__device__ __forceinline__ void gemm_body(
    const unsigned* __restrict__ A, const unsigned* __restrict__ Bm,
    const float* __restrict__ bias, float* __restrict__ C,
    int M, int N, int K, int bx, int by, unsigned* smg)
{
    unsigned* As = smg;                      // [NGSTAGE][ABUF]
    unsigned* Bs = smg + NGSTAGE * ABUF;     // [NGSTAGE][BBUF]

    const int tid  = threadIdx.x;
    const int w    = tid >> 5;
    const int lane = tid & 31;
    const int g    = lane >> 2;
    const int t    = lane & 3;
    const int wm   = (w & 3) * 32;
    const int wn   = (w >> 2) * 64;
    const int brow = by * TBM;
    const int bcol = bx * TBN;

    float acc[2][8][4];
    #pragma unroll
    for (int mt = 0; mt < 2; mt++)
        #pragma unroll
        for (int nt = 0; nt < 8; nt++)
            #pragma unroll
            for (int j = 0; j < 4; j++) acc[mt][nt][j] = 0.f;

    auto load_tile = [&](int k0, int buf) {
        #pragma unroll
        for (int it = 0; it < 4; it++) {
            int i  = it * 256 + tid;
            int m  = i >> 3;
            int c4 = (i & 7) * 4;
            cp16(&As[buf * ABUF + m * ASTR + c4],
                 A + (size_t)(brow + m) * K + k0 + c4);
        }
        #pragma unroll
        for (int it = 0; it < 4; it++) {
            int i  = it * 256 + tid;
            int kk = i >> 5;
            int c4 = (i & 31) * 4;
            cp16(&Bs[buf * BBUF + kk * BSTR + c4],
                 Bm + (size_t)(k0 + kk) * N + bcol + c4);
        }
        cp_commit();
    };

    load_tile(0, 0);
    int buf = 0;
    for (int k0 = 0; k0 < K; k0 += TBK, buf ^= 1) {
        if (k0 + TBK < K) { load_tile(k0 + TBK, buf ^ 1); cp_wait<1>(); }
        else              { cp_wait<0>(); }
        __syncthreads();

        const unsigned* Ab = &As[buf * ABUF];
        const unsigned* Bb = &Bs[buf * BBUF];
        #pragma unroll
        for (int ks = 0; ks < TBK / 8; ks++) {
            unsigned af[2][4];
            #pragma unroll
            for (int mt = 0; mt < 2; mt++) {
                const unsigned* ab = &Ab[(wm + mt * 16) * ASTR + ks * 8];
                af[mt][0] = ab[g * ASTR + t];
                af[mt][1] = ab[(g + 8) * ASTR + t];
                af[mt][2] = ab[g * ASTR + t + 4];
                af[mt][3] = ab[(g + 8) * ASTR + t + 4];
            }
            const unsigned* bb0 = &Bb[(ks * 8 + t) * BSTR + wn + g];
            const unsigned* bb1 = &Bb[(ks * 8 + t + 4) * BSTR + wn + g];
            #pragma unroll
            for (int nt = 0; nt < 8; nt++) {
                unsigned b0 = bb0[nt * 8];
                unsigned b1 = bb1[nt * 8];
                mma_tf32(acc[0][nt], af[0], b0, b1);
                mma_tf32(acc[1][nt], af[1], b0, b1);
            }
        }
        __syncthreads();
    }

    // Epilogue: bias add (+ optional tf32 pre-round), coalesced float2 stores
    #pragma unroll
    for (int mt = 0; mt < 2; mt++) {
        const size_t r0 = (size_t)(brow + wm + mt * 16 + g);
        float* c0 = C + r0 * N;
        float* c1 = c0 + (size_t)8 * N;
        #pragma unroll
        for (int nt = 0; nt < 8; nt++) {
            int nc = bcol + wn + nt * 8 + 2 * t;
            float bx2 = bias[nc], by2 = bias[nc + 1];
            float v00 = acc[mt][nt][0] + bx2, v01 = acc[mt][nt][1] + by2;
            float v10 = acc[mt][nt][2] + bx2, v11 = acc[mt][nt][3] + by2;
            if (ROUND) {
                v00 = __uint_as_float(f2tf32(v00));
                v01 = __uint_as_float(f2tf32(v01));
                v10 = __uint_as_float(f2tf32(v10));
                v11 = __uint_as_float(f2tf32(v11));
            }
            *(float2*)&c0[nc] = make_float2(v00, v01);
            *(float2*)&c1[nc] = make_float2(v10, v11);
        }
    }
}

// Fused kv-proj + q-proj: blocks [0,512) do kv (N=2048), [512,768) do q.
__global__ __launch_bounds__(256) void proj_fused_kernel(
    const unsigned* __restrict__ xc, const unsigned* __restrict__ wkv,
    const float* __restrict__ bkv, float* __restrict__ kvp,
    const unsigned* __restrict__ yc, const unsigned* __restrict__ wq,
    const float* __restrict__ bq, float* __restrict__ qp)
{
    extern __shared__ unsigned smg[];
    int bid = blockIdx.x;
    if (bid < 512) {
        gemm_body<1>(xc, wkv, bkv, kvp, MR, 2 * DD, DD, bid & 15, bid >> 4, smg);
    } else {
        int r = bid - 512;
        gemm_body<1>(yc, wq, bq, qp, MR, DD, DD, r & 7, r >> 3, smg);
    }
}

// Plain single GEMM (o-projection, no rounding)
__global__ __launch_bounds__(256) void gemm_single_kernel(
    const unsigned* __restrict__ A, const unsigned* __restrict__ Bm,
    const float* __restrict__ bias, float* __restrict__ C,
    int M, int N, int K)
{
    extern __shared__ unsigned smg[];
    gemm_body<0>(A, Bm, bias, C, M, N, K, blockIdx.x, blockIdx.y, smg);
}

// ---------------------------------------------------------------------------
// Tensor-core flash attention (R12 winner, unchanged): 256 threads / 8 warps,
// 32 Q-rows per warp (2 m-groups), K/V b-frags shared across both groups.
// 3-stage cp.async, log2-domain softmax.
// ---------------------------------------------------------------------------
#define KSTRIDE 68
#define VSTRIDE 72
#define KBUF (64 * KSTRIDE)
#define VBUF (64 * VSTRIDE)
#define NASTAGE 3
#define ATTN_SMEM (NASTAGE * (KBUF + VBUF) * 4)

__global__ __launch_bounds__(256, 1) void attn_tc_kernel(
    const float* __restrict__ q, const float* __restrict__ kv,
    float* __restrict__ out)
{
    extern __shared__ unsigned sma[];
    unsigned* k_u = sma;
    unsigned* v_u = sma + NASTAGE * KBUF;

    const int tid  = threadIdx.x;
    const int w    = tid >> 5;
    const int lane = tid & 31;
    const int g    = lane >> 2;
    const int t    = lane & 3;
    const int bh   = blockIdx.y;
    const int b    = bh / HH;
    const int h    = bh % HH;
    const int q0   = blockIdx.x * 256;   // BQ=256: 8 warps x 32 rows

    const float* kvbase = kv + (size_t)b * SS * (2 * DD) + h * (2 * HDD);

    auto load_kv = [&](int kt, int buf) {
        #pragma unroll
        for (int it = 0; it < 4; it++) {
            int idx = it * 256 + tid;
            int row = idx >> 4;
            int c4  = (idx & 15) * 4;
            const float* src = kvbase + (size_t)(kt + row) * (2 * DD) + c4;
            cp16(&k_u[buf * KBUF + row * KSTRIDE + c4], src);
            cp16(&v_u[buf * VBUF + row * VSTRIDE + c4], src + HDD);
        }
        cp_commit();
    };

    load_kv(0, 0);
    load_kv(64, 1);

    // Q fragments for both 16-row groups, scaled by 0.125*log2e
    const float QSCALE = 0.125f * 1.4426950408889634f;
    unsigned qa[2][8][4];
    #pragma unroll
    for (int mt = 0; mt < 2; mt++) {
        const float* q0p = q + (size_t)(b * SS + q0 + w * 32 + mt * 16 + g) * DD
                             + h * HDD;
        const float* q1p = q0p + (size_t)8 * DD;
        #pragma unroll
        for (int kj = 0; kj < 8; kj++) {
            qa[mt][kj][0] = __float_as_uint(q0p[8 * kj + t]     * QSCALE);
            qa[mt][kj][1] = __float_as_uint(q1p[8 * kj + t]     * QSCALE);
            qa[mt][kj][2] = __float_as_uint(q0p[8 * kj + t + 4] * QSCALE);
            qa[mt][kj][3] = __float_as_uint(q1p[8 * kj + t + 4] * QSCALE);
        }
    }

    float o[2][8][4];
    #pragma unroll
    for (int mt = 0; mt < 2; mt++)
        #pragma unroll
        for (int i = 0; i < 8; i++)
            #pragma unroll
            for (int j = 0; j < 4; j++) o[mt][i][j] = 0.f;
    float mH[2][2], lH[2][2];
    #pragma unroll
    for (int mt = 0; mt < 2; mt++) {
        mH[mt][0] = -INFINITY; mH[mt][1] = -INFINITY;
        lH[mt][0] = 0.f;       lH[mt][1] = 0.f;
    }

    const int ntiles = SS / 64;
    for (int i = 0; i < ntiles; i++) {
        if (i + 1 < ntiles) cp_wait<1>();
        else                cp_wait<0>();
        __syncthreads();
        if (i + 2 < ntiles) load_kv((i + 2) * 64, (i + 2) % NASTAGE);

        const unsigned* kb = &k_u[(i % NASTAGE) * KBUF];
        const unsigned* vb = &v_u[(i % NASTAGE) * VBUF];

        // S = Q @ K^T : each K b-frag feeds BOTH m-groups
        float s[2][8][4];
        #pragma unroll
        for (int nt = 0; nt < 8; nt++) {
            #pragma unroll
            for (int mt = 0; mt < 2; mt++)
                s[mt][nt][0] = s[mt][nt][1] = s[mt][nt][2] = s[mt][nt][3] = 0.f;
            const unsigned* krow = &kb[(8 * nt + g) * KSTRIDE];
            #pragma unroll
            for (int kj = 0; kj < 8; kj++) {
                unsigned b0 = krow[8 * kj + t];
                unsigned b1 = krow[8 * kj + t + 4];
                mma_tf32(s[0][nt], qa[0][kj], b0, b1);
                mma_tf32(s[1][nt], qa[1][kj], b0, b1);
            }
        }

        // Online softmax (log2 domain), per m-group
        unsigned pa[2][8][4];
        #pragma unroll
        for (int mt = 0; mt < 2; mt++) {
            float rmax0 = -INFINITY, rmax1 = -INFINITY;
            #pragma unroll
            for (int nt = 0; nt < 8; nt++) {
                rmax0 = fmaxf(rmax0, fmaxf(s[mt][nt][0], s[mt][nt][1]));
                rmax1 = fmaxf(rmax1, fmaxf(s[mt][nt][2], s[mt][nt][3]));
            }
            rmax0 = fmaxf(rmax0, __shfl_xor_sync(FULLMASK, rmax0, 1));
            rmax0 = fmaxf(rmax0, __shfl_xor_sync(FULLMASK, rmax0, 2));
            rmax1 = fmaxf(rmax1, __shfl_xor_sync(FULLMASK, rmax1, 1));
            rmax1 = fmaxf(rmax1, __shfl_xor_sync(FULLMASK, rmax1, 2));

            const float mn0 = fmaxf(mH[mt][0], rmax0);
            const float mn1 = fmaxf(mH[mt][1], rmax1);
            const float cr0 = ex2f(mH[mt][0] - mn0);
            const float cr1 = ex2f(mH[mt][1] - mn1);
            mH[mt][0] = mn0; mH[mt][1] = mn1;
            lH[mt][0] *= cr0; lH[mt][1] *= cr1;
            #pragma unroll
            for (int nt = 0; nt < 8; nt++) {
                o[mt][nt][0] *= cr0; o[mt][nt][1] *= cr0;
                o[mt][nt][2] *= cr1; o[mt][nt][3] *= cr1;
            }

            const int srcA = (lane & 28) | (t >> 1);
            const int srcB = srcA | 2;
            const bool odd = (t & 1);
            float ls0 = 0.f, ls1 = 0.f;
            #pragma unroll
            for (int nt = 0; nt < 8; nt++) {
                float p0 = ex2f(s[mt][nt][0] - mn0);
                float p1 = ex2f(s[mt][nt][1] - mn0);
                float p2 = ex2f(s[mt][nt][2] - mn1);
                float p3 = ex2f(s[mt][nt][3] - mn1);
                ls0 += p0 + p1; ls1 += p2 + p3;
                unsigned e0 = f2tf32(p0), e1 = f2tf32(p1);
                unsigned e2 = f2tf32(p2), e3 = f2tf32(p3);
                unsigned u0 = __shfl_sync(FULLMASK, e0, srcA);
                unsigned u1 = __shfl_sync(FULLMASK, e1, srcA);
                unsigned u2 = __shfl_sync(FULLMASK, e2, srcA);
                unsigned u3 = __shfl_sync(FULLMASK, e3, srcA);
                unsigned w0 = __shfl_sync(FULLMASK, e0, srcB);
                unsigned w1 = __shfl_sync(FULLMASK, e1, srcB);
                unsigned w2 = __shfl_sync(FULLMASK, e2, srcB);
                unsigned w3 = __shfl_sync(FULLMASK, e3, srcB);
                pa[mt][nt][0] = odd ? u1 : u0;
                pa[mt][nt][1] = odd ? u3 : u2;
                pa[mt][nt][2] = odd ? w1 : w0;
                pa[mt][nt][3] = odd ? w3 : w2;
            }
            ls0 += __shfl_xor_sync(FULLMASK, ls0, 1);
            ls0 += __shfl_xor_sync(FULLMASK, ls0, 2);
            ls1 += __shfl_xor_sync(FULLMASK, ls1, 1);
            ls1 += __shfl_xor_sync(FULLMASK, ls1, 2);
            lH[mt][0] += ls0; lH[mt][1] += ls1;
        }

        // O += P @ V : each V b-frag feeds BOTH m-groups
        #pragma unroll
        for (int nd = 0; nd < 8; nd++) {
            #pragma unroll
            for (int kj = 0; kj < 8; kj++) {
                unsigned b0 = vb[(8 * kj + t)     * VSTRIDE + 8 * nd + g];
                unsigned b1 = vb[(8 * kj + t + 4) * VSTRIDE + 8 * nd + g];
                mma_tf32(o[0][nd], pa[0][kj], b0, b1);
                mma_tf32(o[1][nd], pa[1][kj], b0, b1);
            }
        }
    }

    // normalize + pre-round + store in (B,H,S,HD) layout
    #pragma unroll
    for (int mt = 0; mt < 2; mt++) {
        const float inv0 = 1.f / lH[mt][0];
        const float inv1 = 1.f / lH[mt][1];
        const size_t r0 = (size_t)(b * HH + h) * SS + q0 + w * 32 + mt * 16 + g;
        float* o0 = out + r0 * HDD;
        float* o1 = o0 + (size_t)8 * HDD;
        #pragma unroll
        for (int nt = 0; nt < 8; nt++) {
            int col = 8 * nt + 2 * t;
            float2 t0 = make_float2(__uint_as_float(f2tf32(o[mt][nt][0] * inv0)),
                                    __uint_as_float(f2tf32(o[mt][nt][1] * inv0)));
            float2 t1 = make_float2(__uint_as_float(f2tf32(o[mt][nt][2] * inv1)),
                                    __uint_as_float(f2tf32(o[mt][nt][3] * inv1)));
            *(float2*)&o0[col] = t0;
            *(float2*)&o1[col] = t1;
        }
    }
}

// ---------------------------------------------------------------------------
extern "C" void kernel_launch(void* const* d_in, const int* in_sizes, int n_in,
                              void* d_out, int out_size)
{
    const float* x    = (const float*)d_in[0];
    const float* y    = (const float*)d_in[1];
    const float* W_kv = (const float*)d_in[2];
    const float* b_kv = (const float*)d_in[3];
    const float* W_q  = (const float*)d_in[4];
    const float* b_q  = (const float*)d_in[5];
    const float* W_o  = (const float*)d_in[6];
    const float* b_o  = (const float*)d_in[7];
    float* out = (float*)d_out;

    float *kvp, *qp, *avp;
    unsigned *xc, *yc, *wkvc, *wqc, *woc;
    cudaGetSymbolAddress((void**)&kvp,  g_kv);
    cudaGetSymbolAddress((void**)&qp,   g_q);
    cudaGetSymbolAddress((void**)&avp,  g_av);
    cudaGetSymbolAddress((void**)&xc,   g_xc);
    cudaGetSymbolAddress((void**)&yc,   g_yc);
    cudaGetSymbolAddress((void**)&wkvc, g_wkvc);
    cudaGetSymbolAddress((void**)&wqc,  g_wqc);
    cudaGetSymbolAddress((void**)&woc,  g_woc);

    cudaFuncSetAttribute(proj_fused_kernel,
        cudaFuncAttributeMaxDynamicSharedMemorySize, GEMM_SMEM);
    cudaFuncSetAttribute(gemm_single_kernel,
        cudaFuncAttributeMaxDynamicSharedMemorySize, GEMM_SMEM);
    cudaFuncSetAttribute(attn_tc_kernel,
        cudaFuncAttributeMaxDynamicSharedMemorySize, ATTN_SMEM);
    // Request maximum smem carveout so two 71.7KB CTAs co-reside per SM.
    cudaFuncSetAttribute(proj_fused_kernel,
        cudaFuncAttributePreferredSharedMemoryCarveout, 100);
    cudaFuncSetAttribute(gemm_single_kernel,
        cudaFuncAttributePreferredSharedMemoryCarveout, 100);

    // Single fused pre-round pass for all 5 tensors
    cvt_all_kernel<<<(N4_TOT + 255) / 256, 256>>>(
        x, xc, y, yc, W_kv, wkvc, W_q, wqc, W_o, woc);

    // Fused kv-proj + q-proj (768 blocks, 2 CTAs/SM), outputs pre-rounded
    proj_fused_kernel<<<768, 256, GEMM_SMEM>>>(
        xc, wkvc, b_kv, kvp, yc, wqc, b_q, qp);

    // fused tensor-core attention (256 threads, 32 rows/warp) -> g_av
    attn_tc_kernel<<<dim3(SS / 256, BB * HH), 256, ATTN_SMEM>>>(
        qp, kvp, avp);

    // out = values @ W_o + b_o [4096 x 1024]
    gemm_single_kernel<<<dim3(DD / TBN, MR / TBM), 256, GEMM_SMEM>>>(
        (const unsigned*)avp, woc, b_o, out, MR, DD, DD);
}

// round 14
// speedup vs baseline: 1.6250x; 1.0159x over previous
#include <cuda_runtime.h>
#include <math.h>
#include <stdint.h>

#define BB 2
#define SS 2048
#define DD 1024
#define HH 16
#define HDD 64
#define MR (BB*SS)   // 4096 rows

// Scratch (allocation-free rule: __device__ globals)
__device__ __align__(16) float    g_kv[MR * 2 * DD];   // kv proj out (tf32-rounded)
__device__ __align__(16) float    g_q [MR * DD];       // q  proj out (tf32-rounded)
__device__ __align__(16) float    g_av[MR * DD];       // attn out (B,H,S,HD), rounded
__device__ __align__(16) unsigned g_xc  [MR * DD];     // x     tf32 bits
__device__ __align__(16) unsigned g_yc  [MR * DD];     // y     tf32 bits
__device__ __align__(16) unsigned g_wkvc[DD * 2 * DD]; // W_kv  tf32 bits
__device__ __align__(16) unsigned g_wqc [DD * DD];     // W_q   tf32 bits
__device__ __align__(16) unsigned g_woc [DD * DD];     // W_o   tf32 bits

#define FULLMASK 0xffffffffu

__device__ __forceinline__ unsigned f2tf32(float f) {
    unsigned u;
    asm("cvt.rna.tf32.f32 %0, %1;" : "=r"(u) : "f"(f));
    return u;
}

__device__ __forceinline__ float ex2f(float x) {
    float y;
    asm("ex2.approx.f32 %0, %1;" : "=f"(y) : "f"(x));
    return y;
}

__device__ __forceinline__ void mma_tf32(float* d, const unsigned* a,
                                         unsigned b0, unsigned b1) {
    asm volatile(
        "mma.sync.aligned.m16n8k8.row.col.f32.tf32.tf32.f32 "
        "{%0,%1,%2,%3}, {%4,%5,%6,%7}, {%8,%9}, {%0,%1,%2,%3};\n"
        : "+f"(d[0]), "+f"(d[1]), "+f"(d[2]), "+f"(d[3])
        : "r"(a[0]), "r"(a[1]), "r"(a[2]), "r"(a[3]), "r"(b0), "r"(b1));
}

__device__ __forceinline__ void cp16(void* dst_smem, const void* src) {
    unsigned d = (unsigned)__cvta_generic_to_shared(dst_smem);
    asm volatile("cp.async.cg.shared.global [%0], [%1], 16;\n" :: "r"(d), "l"(src));
}
__device__ __forceinline__ void cp_commit() {
    asm volatile("cp.async.commit_group;\n");
}
template <int N> __device__ __forceinline__ void cp_wait() {
    asm volatile("cp.async.wait_group %0;\n" :: "n"(N));
}

// ---------------------------------------------------------------------------
// Single fused pre-round pass for all 5 tensors
// ---------------------------------------------------------------------------
#define N4_X   (MR * DD / 4)
#define N4_WKV (DD * 2 * DD / 4)
#define N4_W   (DD * DD / 4)
#define N4_TOT (2 * N4_X + N4_WKV + 2 * N4_W)

__global__ __launch_bounds__(256) void cvt_all_kernel(
    const float* __restrict__ x,   unsigned* __restrict__ xc,
    const float* __restrict__ y,   unsigned* __restrict__ yc,
    const float* __restrict__ wkv, unsigned* __restrict__ wkvc,
    const float* __restrict__ wq,  unsigned* __restrict__ wqc,
    const float* __restrict__ wo,  unsigned* __restrict__ woc)
{
    int i = blockIdx.x * 256 + threadIdx.x;
    const int E1 = N4_X, E2 = 2 * N4_X, E3 = E2 + N4_WKV, E4 = E3 + N4_W,
              E5 = E4 + N4_W;
    const float* s; unsigned* d; int j;
    if      (i < E1) { s = x;   d = xc;   j = i; }
    else if (i < E2) { s = y;   d = yc;   j = i - E1; }
    else if (i < E3) { s = wkv; d = wkvc; j = i - E2; }
    else if (i < E4) { s = wq;  d = wqc;  j = i - E3; }
    else if (i < E5) { s = wo;  d = woc;  j = i - E4; }
    else return;
    float4 v = *(const float4*)(s + 4 * (size_t)j);
    uint4 u = make_uint4(f2tf32(v.x), f2tf32(v.y), f2tf32(v.z), f2tf32(v.w));
    *(uint4*)(d + 4 * (size_t)j) = u;
}

// ---------------------------------------------------------------------------
// Tensor-core tf32 GEMM body, 2-stage cp.async (R13 config, unchanged).
// ---------------------------------------------------------------------------
#define TBM 128
#define TBN 128
#define TBK 32
#define ASTR 36
#define BSTR 136
#define ABUF (TBM * ASTR)   // 4608 words
#define BBUF (TBK * BSTR)   // 4352 words
#define NGSTAGE 2
#define GEMM_SMEM (NGSTAGE * (ABUF + BBUF) * 4)  // 71680 bytes

template <int ROUND>
__device__ __forceinline__ void gemm_body(
    const unsigned* __restrict__ A, const unsigned* __restrict__ Bm,
    const float* __restrict__ bias, float* __restrict__ C,
    int M, int N, int K, int bx, int by, unsigned* smg)
{
    unsigned* As = smg;                      // [NGSTAGE][ABUF]
    unsigned* Bs = smg + NGSTAGE * ABUF;     // [NGSTAGE][BBUF]

    const int tid  = threadIdx.x;
    const int w    = tid >> 5;
    const int lane = tid & 31;
    const int g    = lane >> 2;
    const int t    = lane & 3;
    const int wm   = (w & 3) * 32;
    const int wn   = (w >> 2) * 64;
    const int brow = by * TBM;
    const int bcol = bx * TBN;

    float acc[2][8][4];
    #pragma unroll
    for (int mt = 0; mt < 2; mt++)
        #pragma unroll
        for (int nt = 0; nt < 8; nt++)
            #pragma unroll
            for (int j = 0; j < 4; j++) acc[mt][nt][j] = 0.f;

    auto load_tile = [&](int k0, int buf) {
        #pragma unroll
        for (int it = 0; it < 4; it++) {
            int i  = it * 256 + tid;
            int m  = i >> 3;
            int c4 = (i & 7) * 4;
            cp16(&As[buf * ABUF + m * ASTR + c4],
                 A + (size_t)(brow + m) * K + k0 + c4);
        }
        #pragma unroll
        for (int it = 0; it < 4; it++) {
            int i  = it * 256 + tid;
            int kk = i >> 5;
            int c4 = (i & 31) * 4;
            cp16(&Bs[buf * BBUF + kk * BSTR + c4],
                 Bm + (size_t)(k0 + kk) * N + bcol + c4);
        }
        cp_commit();
    };

    load_tile(0, 0);
    int buf = 0;
    for (int k0 = 0; k0 < K; k0 += TBK, buf ^= 1) {
        if (k0 + TBK < K) { load_tile(k0 + TBK, buf ^ 1); cp_wait<1>(); }
        else              { cp_wait<0>(); }
        __syncthreads();

        const unsigned* Ab = &As[buf * ABUF];
        const unsigned* Bb = &Bs[buf * BBUF];
        #pragma unroll
        for (int ks = 0; ks < TBK / 8; ks++) {
            unsigned af[2][4];
            #pragma unroll
            for (int mt = 0; mt < 2; mt++) {
                const unsigned* ab = &Ab[(wm + mt * 16) * ASTR + ks * 8];
                af[mt][0] = ab[g * ASTR + t];
                af[mt][1] = ab[(g + 8) * ASTR + t];
                af[mt][2] = ab[g * ASTR + t + 4];
                af[mt][3] = ab[(g + 8) * ASTR + t + 4];
            }
            const unsigned* bb0 = &Bb[(ks * 8 + t) * BSTR + wn + g];
            const unsigned* bb1 = &Bb[(ks * 8 + t + 4) * BSTR + wn + g];
            #pragma unroll
            for (int nt = 0; nt < 8; nt++) {
                unsigned b0 = bb0[nt * 8];
                unsigned b1 = bb1[nt * 8];
                mma_tf32(acc[0][nt], af[0], b0, b1);
                mma_tf32(acc[1][nt], af[1], b0, b1);
            }
        }
        __syncthreads();
    }

    // Epilogue: bias add (+ optional tf32 pre-round), coalesced float2 stores
    #pragma unroll
    for (int mt = 0; mt < 2; mt++) {
        const size_t r0 = (size_t)(brow + wm + mt * 16 + g);
        float* c0 = C + r0 * N;
        float* c1 = c0 + (size_t)8 * N;
        #pragma unroll
        for (int nt = 0; nt < 8; nt++) {
            int nc = bcol + wn + nt * 8 + 2 * t;
            float bx2 = bias[nc], by2 = bias[nc + 1];
            float v00 = acc[mt][nt][0] + bx2, v01 = acc[mt][nt][1] + by2;
            float v10 = acc[mt][nt][2] + bx2, v11 = acc[mt][nt][3] + by2;
            if (ROUND) {
                v00 = __uint_as_float(f2tf32(v00));
                v01 = __uint_as_float(f2tf32(v01));
                v10 = __uint_as_float(f2tf32(v10));
                v11 = __uint_as_float(f2tf32(v11));
            }
            *(float2*)&c0[nc] = make_float2(v00, v01);
            *(float2*)&c1[nc] = make_float2(v10, v11);
        }
    }
}

// Fused kv-proj + q-proj: blocks [0,512) do kv (N=2048), [512,768) do q.
__global__ __launch_bounds__(256) void proj_fused_kernel(
    const unsigned* __restrict__ xc, const unsigned* __restrict__ wkv,
    const float* __restrict__ bkv, float* __restrict__ kvp,
    const unsigned* __restrict__ yc, const unsigned* __restrict__ wq,
    const float* __restrict__ bq, float* __restrict__ qp)
{
    extern __shared__ unsigned smg[];
    int bid = blockIdx.x;
    if (bid < 512) {
        gemm_body<1>(xc, wkv, bkv, kvp, MR, 2 * DD, DD, bid & 15, bid >> 4, smg);
    } else {
        int r = bid - 512;
        gemm_body<1>(yc, wq, bq, qp, MR, DD, DD, r & 7, r >> 3, smg);
    }
}

// Plain single GEMM (o-projection, no rounding)
__global__ __launch_bounds__(256) void gemm_single_kernel(
    const unsigned* __restrict__ A, const unsigned* __restrict__ Bm,
    const float* __restrict__ bias, float* __restrict__ C,
    int M, int N, int K)
{
    extern __shared__ unsigned smg[];
    gemm_body<0>(A, Bm, bias, C, M, N, K, blockIdx.x, blockIdx.y, smg);
}

// ---------------------------------------------------------------------------
// Tensor-core flash attention: 256 threads / 8 warps, 32 Q-rows per warp,
// 3-stage cp.async, log2-domain softmax.
// NEW: shuffle-free P->A-fragment conversion. V rows are permuted within
// each 8-row group at the cp.async store (perm [0,4,1,5,2,6,3,7]) so the
// MMA k-slot bijection sigma(t)=2t, sigma(t+4)=2t+1 makes the exp'd
// accumulator registers directly usable as A-fragments: pa = {e0,e2,e1,e3}.
// Removes 128 SHFL + selects per tile per warp.
// ---------------------------------------------------------------------------
#define KSTRIDE 68
#define VSTRIDE 72
#define KBUF (64 * KSTRIDE)
#define VBUF (64 * VSTRIDE)
#define NASTAGE 3
#define ATTN_SMEM (NASTAGE * (KBUF + VBUF) * 4)

__global__ __launch_bounds__(256, 1) void attn_tc_kernel(
    const float* __restrict__ q, const float* __restrict__ kv,
    float* __restrict__ out)
{
    extern __shared__ unsigned sma[];
    unsigned* k_u = sma;
    unsigned* v_u = sma + NASTAGE * KBUF;

    const int tid  = threadIdx.x;
    const int w    = tid >> 5;
    const int lane = tid & 31;
    const int g    = lane >> 2;
    const int t    = lane & 3;
    const int bh   = blockIdx.y;
    const int b    = bh / HH;
    const int h    = bh % HH;
    const int q0   = blockIdx.x * 256;   // BQ=256: 8 warps x 32 rows

    const float* kvbase = kv + (size_t)b * SS * (2 * DD) + h * (2 * HDD);

    auto load_kv = [&](int kt, int buf) {
        #pragma unroll
        for (int it = 0; it < 4; it++) {
            int idx = it * 256 + tid;
            int row = idx >> 4;
            int c4  = (idx & 15) * 4;
            const float* src = kvbase + (size_t)(kt + row) * (2 * DD) + c4;
            cp16(&k_u[buf * KBUF + row * KSTRIDE + c4], src);
            // V row permutation within 8-row groups: pos even -> pos/2,
            // pos odd -> 4 + pos/2  (inverse of sigma)
            int pos = row & 7;
            int rp  = (row & ~7) | ((pos & 1) ? (4 + (pos >> 1)) : (pos >> 1));
            cp16(&v_u[buf * VBUF + rp * VSTRIDE + c4], src + HDD);
        }
        cp_commit();
    };

    load_kv(0, 0);
    load_kv(64, 1);

    // Q fragments for both 16-row groups, scaled by 0.125*log2e
    const float QSCALE = 0.125f * 1.4426950408889634f;
    unsigned qa[2][8][4];
    #pragma unroll
    for (int mt = 0; mt < 2; mt++) {
        const float* q0p = q + (size_t)(b * SS + q0 + w * 32 + mt * 16 + g) * DD
                             + h * HDD;
        const float* q1p = q0p + (size_t)8 * DD;
        #pragma unroll
        for (int kj = 0; kj < 8; kj++) {
            qa[mt][kj][0] = __float_as_uint(q0p[8 * kj + t]     * QSCALE);
            qa[mt][kj][1] = __float_as_uint(q1p[8 * kj + t]     * QSCALE);
            qa[mt][kj][2] = __float_as_uint(q0p[8 * kj + t + 4] * QSCALE);
            qa[mt][kj][3] = __float_as_uint(q1p[8 * kj + t + 4] * QSCALE);
        }
    }

    float o[2][8][4];
    #pragma unroll
    for (int mt = 0; mt < 2; mt++)
        #pragma unroll
        for (int i = 0; i < 8; i++)
            #pragma unroll
            for (int j = 0; j < 4; j++) o[mt][i][j] = 0.f;
    float mH[2][2], lH[2][2];
    #pragma unroll
    for (int mt = 0; mt < 2; mt++) {
        mH[mt][0] = -INFINITY; mH[mt][1] = -INFINITY;
        lH[mt][0] = 0.f;       lH[mt][1] = 0.f;
    }

    const int ntiles = SS / 64;
    for (int i = 0; i < ntiles; i++) {
        if (i + 1 < ntiles) cp_wait<1>();
        else                cp_wait<0>();
        __syncthreads();
        if (i + 2 < ntiles) load_kv((i + 2) * 64, (i + 2) % NASTAGE);

        const unsigned* kb = &k_u[(i % NASTAGE) * KBUF];
        const unsigned* vb = &v_u[(i % NASTAGE) * VBUF];

        // S = Q @ K^T : each K b-frag feeds BOTH m-groups
        float s[2][8][4];
        #pragma unroll
        for (int nt = 0; nt < 8; nt++) {
            #pragma unroll
            for (int mt = 0; mt < 2; mt++)
                s[mt][nt][0] = s[mt][nt][1] = s[mt][nt][2] = s[mt][nt][3] = 0.f;
            const unsigned* krow = &kb[(8 * nt + g) * KSTRIDE];
            #pragma unroll
            for (int kj = 0; kj < 8; kj++) {
                unsigned b0 = krow[8 * kj + t];
                unsigned b1 = krow[8 * kj + t + 4];
                mma_tf32(s[0][nt], qa[0][kj], b0, b1);
                mma_tf32(s[1][nt], qa[1][kj], b0, b1);
            }
        }

        // Online softmax (log2 domain), per m-group — shuffle-free P frags
        unsigned pa[2][8][4];
        #pragma unroll
        for (int mt = 0; mt < 2; mt++) {
            float rmax0 = -INFINITY, rmax1 = -INFINITY;
            #pragma unroll
            for (int nt = 0; nt < 8; nt++) {
                rmax0 = fmaxf(rmax0, fmaxf(s[mt][nt][0], s[mt][nt][1]));
                rmax1 = fmaxf(rmax1, fmaxf(s[mt][nt][2], s[mt][nt][3]));
            }
            rmax0 = fmaxf(rmax0, __shfl_xor_sync(FULLMASK, rmax0, 1));
            rmax0 = fmaxf(rmax0, __shfl_xor_sync(FULLMASK, rmax0, 2));
            rmax1 = fmaxf(rmax1, __shfl_xor_sync(FULLMASK, rmax1, 1));
            rmax1 = fmaxf(rmax1, __shfl_xor_sync(FULLMASK, rmax1, 2));

            const float mn0 = fmaxf(mH[mt][0], rmax0);
            const float mn1 = fmaxf(mH[mt][1], rmax1);
            const float cr0 = ex2f(mH[mt][0] - mn0);
            const float cr1 = ex2f(mH[mt][1] - mn1);
            mH[mt][0] = mn0; mH[mt][1] = mn1;
            lH[mt][0] *= cr0; lH[mt][1] *= cr1;
            #pragma unroll
            for (int nt = 0; nt < 8; nt++) {
                o[mt][nt][0] *= cr0; o[mt][nt][1] *= cr0;
                o[mt][nt][2] *= cr1; o[mt][nt][3] *= cr1;
            }

            float ls0 = 0.f, ls1 = 0.f;
            #pragma unroll
            for (int nt = 0; nt < 8; nt++) {
                float p0 = ex2f(s[mt][nt][0] - mn0);   // (row g,   col 2t)
                float p1 = ex2f(s[mt][nt][1] - mn0);   // (row g,   col 2t+1)
                float p2 = ex2f(s[mt][nt][2] - mn1);   // (row g+8, col 2t)
                float p3 = ex2f(s[mt][nt][3] - mn1);   // (row g+8, col 2t+1)
                ls0 += p0 + p1; ls1 += p2 + p3;
                // A-frag slots under sigma: slot t <- col 2t, slot t+4 <- col 2t+1
                pa[mt][nt][0] = f2tf32(p0);
                pa[mt][nt][1] = f2tf32(p2);
                pa[mt][nt][2] = f2tf32(p1);
                pa[mt][nt][3] = f2tf32(p3);
            }
            ls0 += __shfl_xor_sync(FULLMASK, ls0, 1);
            ls0 += __shfl_xor_sync(FULLMASK, ls0, 2);
            ls1 += __shfl_xor_sync(FULLMASK, ls1, 1);
            ls1 += __shfl_xor_sync(FULLMASK, ls1, 2);
            lH[mt][0] += ls0; lH[mt][1] += ls1;
        }

        // O += P @ V : V rows permuted in smem to match sigma
        #pragma unroll
        for (int nd = 0; nd < 8; nd++) {
            #pragma unroll
            for (int kj = 0; kj < 8; kj++) {
                unsigned b0 = vb[(8 * kj + t)     * VSTRIDE + 8 * nd + g];
                unsigned b1 = vb[(8 * kj + t + 4) * VSTRIDE + 8 * nd + g];
                mma_tf32(o[0][nd], pa[0][kj], b0, b1);
                mma_tf32(o[1][nd], pa[1][kj], b0, b1);
            }
        }
    }

    // normalize + pre-round + store in (B,H,S,HD) layout
    #pragma unroll
    for (int mt = 0; mt < 2; mt++) {
        const float inv0 = 1.f / lH[mt][0];
        const float inv1 = 1.f / lH[mt][1];
        const size_t r0 = (size_t)(b * HH + h) * SS + q0 + w * 32 + mt * 16 + g;
        float* o0 = out + r0 * HDD;
        float* o1 = o0 + (size_t)8 * HDD;
        #pragma unroll
        for (int nt = 0; nt < 8; nt++) {
            int col = 8 * nt + 2 * t;
            float2 t0 = make_float2(__uint_as_float(f2tf32(o[mt][nt][0] * inv0)),
                                    __uint_as_float(f2tf32(o[mt][nt][1] * inv0)));
            float2 t1 = make_float2(__uint_as_float(f2tf32(o[mt][nt][2] * inv1)),
                                    __uint_as_float(f2tf32(o[mt][nt][3] * inv1)));
            *(float2*)&o0[col] = t0;
            *(float2*)&o1[col] = t1;
        }
    }
}

// ---------------------------------------------------------------------------
extern "C" void kernel_launch(void* const* d_in, const int* in_sizes, int n_in,
                              void* d_out, int out_size)
{
    const float* x    = (const float*)d_in[0];
    const float* y    = (const float*)d_in[1];
    const float* W_kv = (const float*)d_in[2];
    const float* b_kv = (const float*)d_in[3];
    const float* W_q  = (const float*)d_in[4];
    const float* b_q  = (const float*)d_in[5];
    const float* W_o  = (const float*)d_in[6];
    const float* b_o  = (const float*)d_in[7];
    float* out = (float*)d_out;

    float *kvp, *qp, *avp;
    unsigned *xc, *yc, *wkvc, *wqc, *woc;
    cudaGetSymbolAddress((void**)&kvp,  g_kv);
    cudaGetSymbolAddress((void**)&qp,   g_q);
    cudaGetSymbolAddress((void**)&avp,  g_av);
    cudaGetSymbolAddress((void**)&xc,   g_xc);
    cudaGetSymbolAddress((void**)&yc,   g_yc);
    cudaGetSymbolAddress((void**)&wkvc, g_wkvc);
    cudaGetSymbolAddress((void**)&wqc,  g_wqc);
    cudaGetSymbolAddress((void**)&woc,  g_woc);

    cudaFuncSetAttribute(proj_fused_kernel,
        cudaFuncAttributeMaxDynamicSharedMemorySize, GEMM_SMEM);
    cudaFuncSetAttribute(gemm_single_kernel,
        cudaFuncAttributeMaxDynamicSharedMemorySize, GEMM_SMEM);
    cudaFuncSetAttribute(attn_tc_kernel,
        cudaFuncAttributeMaxDynamicSharedMemorySize, ATTN_SMEM);
    cudaFuncSetAttribute(proj_fused_kernel,
        cudaFuncAttributePreferredSharedMemoryCarveout, 100);
    cudaFuncSetAttribute(gemm_single_kernel,
        cudaFuncAttributePreferredSharedMemoryCarveout, 100);

    // Single fused pre-round pass for all 5 tensors
    cvt_all_kernel<<<(N4_TOT + 255) / 256, 256>>>(
        x, xc, y, yc, W_kv, wkvc, W_q, wqc, W_o, woc);

    // Fused kv-proj + q-proj (768 blocks), outputs pre-rounded
    proj_fused_kernel<<<768, 256, GEMM_SMEM>>>(
        xc, wkvc, b_kv, kvp, yc, wqc, b_q, qp);

    // fused tensor-core attention (256 threads, 32 rows/warp) -> g_av
    attn_tc_kernel<<<dim3(SS / 256, BB * HH), 256, ATTN_SMEM>>>(
        qp, kvp, avp);

    // out = values @ W_o + b_o [4096 x 1024]
    gemm_single_kernel<<<dim3(DD / TBN, MR / TBM), 256, GEMM_SMEM>>>(
        (const unsigned*)avp, woc, b_o, out, MR, DD, DD);
}